// round 17
// baseline (speedup 1.0000x reference)
#include <cuda_runtime.h>
#include <cuda_bf16.h>
#include <cuda_fp16.h>
#include <cstdint>
#include <math.h>

#define B_ 4
#define W_ 1024
#define C_ 1024
#define H_ 16
#define D_ 64

// Static device scratch (allocation-free rule).
__device__ __half g_xh[4096 * 1024];          // x fp16
__device__ __half g_wqh[1024 * 1024], g_wkh[1024 * 1024], g_wvh2[1024 * 1024];
__device__ __half g_woh[1024 * 1024];
__device__ __half g_erh[64 * 1024];           // er fp16
__device__ __half g_avh[4096 * 1024];         // av fp16 [b][w][c]
__device__ __half g_qh[B_ * H_ * W_ * D_];    // [b][h][w][d]  (pre-scaled log2e/32)
__device__ __half g_kh[B_ * H_ * W_ * D_];
__device__ __half g_vh[B_ * H_ * W_ * D_];

// ---------------------------------------------------------------------------
// helpers
// ---------------------------------------------------------------------------
__device__ __forceinline__ uint32_t smem_to_u32(const void* p) {
    uint32_t a;
    asm("{ .reg .u64 t; cvta.to.shared.u64 t, %1; cvt.u32.u64 %0, t; }"
        : "=r"(a) : "l"(p));
    return a;
}
__device__ __forceinline__ void cp_async16(uint32_t s, const void* g) {
    asm volatile("cp.async.cg.shared.global [%0], [%1], 16;" :: "r"(s), "l"(g));
}
#define CP_COMMIT() asm volatile("cp.async.commit_group;" ::: "memory")
#define CP_WAIT(n)  asm volatile("cp.async.wait_group %0;" :: "n"(n) : "memory")

#define LDSM_X4(r0, r1, r2, r3, addr) \
    asm volatile("ldmatrix.sync.aligned.m8n8.x4.shared.b16 {%0,%1,%2,%3}, [%4];" \
        : "=r"(r0), "=r"(r1), "=r"(r2), "=r"(r3) : "r"(addr))
#define LDSM_X4T(r0, r1, r2, r3, addr) \
    asm volatile("ldmatrix.sync.aligned.m8n8.x4.trans.shared.b16 {%0,%1,%2,%3}, [%4];" \
        : "=r"(r0), "=r"(r1), "=r"(r2), "=r"(r3) : "r"(addr))

__device__ __forceinline__ void mma_f16(float* c, const uint32_t* a,
                                        uint32_t b0, uint32_t b1) {
    asm volatile(
        "mma.sync.aligned.m16n8k16.row.col.f32.f16.f16.f32 "
        "{%0,%1,%2,%3}, {%4,%5,%6,%7}, {%8,%9}, {%0,%1,%2,%3};"
        : "+f"(c[0]), "+f"(c[1]), "+f"(c[2]), "+f"(c[3])
        : "r"(a[0]), "r"(a[1]), "r"(a[2]), "r"(a[3]), "r"(b0), "r"(b1));
}
__device__ __forceinline__ uint32_t pkh(float a, float b) {
    __half2 t = __floats2half2_rn(a, b);
    return *(uint32_t*)&t;
}

// ---------------------------------------------------------------------------
// Convert: x + Wq + Wk + Wv + Wo + er -> fp16 planes (single pass each).
// ---------------------------------------------------------------------------
__global__ __launch_bounds__(256) void cvt_all(const float* __restrict__ x,
                                               const float* __restrict__ Wq,
                                               const float* __restrict__ Wk,
                                               const float* __restrict__ Wv,
                                               const float* __restrict__ Wo,
                                               const float* __restrict__ er) {
    int blk = blockIdx.x;
    const float* src;
    __half* dst;
    int lb;
    if (blk < 4096)      { src = x;  dst = g_xh;   lb = blk; }
    else if (blk < 5120) { src = Wq; dst = g_wqh;  lb = blk - 4096; }
    else if (blk < 6144) { src = Wk; dst = g_wkh;  lb = blk - 5120; }
    else if (blk < 7168) { src = Wv; dst = g_wvh2; lb = blk - 6144; }
    else if (blk < 8192) { src = Wo; dst = g_woh;  lb = blk - 7168; }
    else                 { src = er; dst = g_erh;  lb = blk - 8192; }
    int i = lb * 256 + threadIdx.x;
    float4 f = ((const float4*)src)[i];
    ((uint32_t*)dst)[i * 2]     = pkh(f.x, f.y);
    ((uint32_t*)dst)[i * 2 + 1] = pkh(f.z, f.w);
}

// ---------------------------------------------------------------------------
// cp.async fp16 GEMM (unchanged from R15).
// ---------------------------------------------------------------------------
#define GA_STAGE 16384
#define GEMM_SMEM (4 * GA_STAGE)   // 65536

template <int MODE>
__global__ __launch_bounds__(256, 2) void gemm_f16a(
        const float* __restrict__ b0, const float* __restrict__ b1,
        const float* __restrict__ b2, float* __restrict__ Cout) {
    extern __shared__ char smem[];
    const uint32_t sb = smem_to_u32(smem);
    const int tid = threadIdx.x;
    const int lane = tid & 31;
    const int wid = tid >> 5;
    const int wm = wid & 1;
    const int wn = wid >> 1;
    const int row0 = blockIdx.y * 128;
    const int col0 = blockIdx.x * 128;
    const int z = (MODE == 0) ? (int)blockIdx.z : 3;
    const __half* Ap = (MODE == 0) ? g_xh : g_avh;
    const __half* Bp = (z == 0) ? g_wqh : (z == 1) ? g_wkh : (z == 2) ? g_wvh2 : g_woh;
    const float* bias = (MODE == 1) ? b0 : (z == 0 ? b0 : (z == 1 ? b1 : b2));

    auto prefetch = [&](int ch, int stg) {
        const uint32_t stA = sb + stg * GA_STAGE;
        const uint32_t stB = stA + 8192;
#pragma unroll
        for (int i = 0; i < 2; i++) {
            int idx = tid + i * 256;
            int r = idx >> 2, c = idx & 3;
            uint32_t off = r * 64 + ((c ^ ((r >> 1) & 3)) * 16);
            cp_async16(stA + off, Ap + (size_t)(row0 + r) * 1024 + ch * 32 + c * 8);
            cp_async16(stB + off, Bp + (size_t)(col0 + r) * 1024 + ch * 32 + c * 8);
        }
    };

    float acc[4][4][4];
#pragma unroll
    for (int mt = 0; mt < 4; mt++)
#pragma unroll
        for (int nt = 0; nt < 4; nt++)
#pragma unroll
            for (int i = 0; i < 4; i++) acc[mt][nt][i] = 0.f;

    const int a_rowoff = (lane & 7) + ((lane >> 3) & 1) * 8;
    const int a_csel   = lane >> 4;
    const int b_rowoff = ((lane >> 4) << 3) + (lane & 7);
    const int b_csel   = (lane >> 3) & 1;

    auto do_mma = [&](int stg) {
        const uint32_t stA = sb + stg * GA_STAGE;
        const uint32_t stB = stA + 8192;
#pragma unroll
        for (int ks = 0; ks < 2; ks++) {
            uint32_t ah[4][4], bh[2][4];
#pragma unroll
            for (int mt = 0; mt < 4; mt++) {
                int row = wm * 64 + mt * 16 + a_rowoff;
                int chunk = ks * 2 + a_csel;
                LDSM_X4(ah[mt][0], ah[mt][1], ah[mt][2], ah[mt][3],
                        stA + row * 64 + ((chunk ^ ((row >> 1) & 3)) * 16));
            }
#pragma unroll
            for (int n2 = 0; n2 < 2; n2++) {
                int row = wn * 32 + n2 * 16 + b_rowoff;
                int chunk = ks * 2 + b_csel;
                LDSM_X4(bh[n2][0], bh[n2][1], bh[n2][2], bh[n2][3],
                        stB + row * 64 + ((chunk ^ ((row >> 1) & 3)) * 16));
            }
#pragma unroll
            for (int mt = 0; mt < 4; mt++)
#pragma unroll
                for (int nt = 0; nt < 4; nt++)
                    mma_f16(acc[mt][nt], ah[mt],
                            bh[nt >> 1][(nt & 1) * 2], bh[nt >> 1][(nt & 1) * 2 + 1]);
        }
    };

    prefetch(0, 0); CP_COMMIT();
    prefetch(1, 1); CP_COMMIT();
    prefetch(2, 2); CP_COMMIT();
    for (int ch = 0; ch < 32; ch++) {
        if (ch < 30)      { CP_WAIT(2); }
        else if (ch == 30){ CP_WAIT(1); }
        else              { CP_WAIT(0); }
        __syncthreads();
        if (ch + 3 < 32) { prefetch(ch + 3, (ch + 3) & 3); CP_COMMIT(); }
        do_mma(ch & 3);
    }

    const int g = lane >> 2;
    const int cpair = (lane & 3) * 2;
#pragma unroll
    for (int mt = 0; mt < 4; mt++) {
#pragma unroll
        for (int nt = 0; nt < 4; nt++) {
            int col = col0 + wn * 32 + nt * 8 + cpair;
            float2 bi = *(const float2*)(bias + col);
            int r0 = row0 + wm * 64 + mt * 16 + g;
            int r1 = r0 + 8;
            float2 v0 = make_float2(acc[mt][nt][0] + bi.x, acc[mt][nt][1] + bi.y);
            float2 v1 = make_float2(acc[mt][nt][2] + bi.x, acc[mt][nt][3] + bi.y);
            if (MODE == 1) {
                *(float2*)(Cout + (size_t)r0 * 1024 + col) = v0;
                *(float2*)(Cout + (size_t)r1 * 1024 + col) = v1;
            } else {
                if (z == 0) {   // fold (1/sqrt(c)) * log2(e) into q -> exp2 logits
                    const float qs = 0.045084439f;   // 1.44269504f / 32
                    v0.x *= qs; v0.y *= qs; v1.x *= qs; v1.y *= qs;
                }
                int h = col >> 6, d0 = col & 63;
                size_t i0 = (((size_t)((r0 >> 10) * H_ + h)) * W_ + (r0 & 1023)) * D_ + d0;
                size_t i1 = (((size_t)((r1 >> 10) * H_ + h)) * W_ + (r1 & 1023)) * D_ + d0;
                __half* dst = (z == 0) ? g_qh : (z == 1) ? g_kh : g_vh;
                *(uint32_t*)(dst + i0) = pkh(v0.x, v0.y);
                *(uint32_t*)(dst + i1) = pkh(v1.x, v1.y);
            }
        }
    }
}

// ---------------------------------------------------------------------------
// Tensor-core flash attention, 2-D warp tiling (4 M-warps x 2 N-warps).
// Each warp: 32-row x 64-col S tile; partial l / partial O per N-half,
// combined once in the epilogue via smem (valid since no online max).
// smem: Qw fp16 [128i][64k] @0 (16KB), Et fp16 [64d][128i] @16384 (16KB),
//       stage s (s=0..2) @ 32768 + s*49152: KQ (32KB) + V (16KB)
// Epilogue reuse: L at sb+0 (512B over Qw), O at sb+32768 (stride-66 fp32).
// ---------------------------------------------------------------------------
#define ATTN_STAGE 49152
#define ATTN_SMEM (32768 + 3 * ATTN_STAGE)   // 180224

__global__ __launch_bounds__(256) void attn_mma() {
    extern __shared__ char sm[];
    const uint32_t sb = smem_to_u32(sm);
    const int tid = threadIdx.x;
    const int lane = tid & 31;
    const int warp = tid >> 5;
    const int warpM = warp & 3;
    const int warpN = warp >> 2;
    const int bh = blockIdx.y;
    const int b = bh >> 4, h = bh & 15;
    const int w0 = blockIdx.x * 128;

    const __half* qbh = g_qh + (size_t)bh * W_ * D_;
    const __half* kbh = g_kh + (size_t)bh * W_ * D_;
    const __half* vhb = g_vh + (size_t)bh * W_ * D_;

    // Qw tile (async)
#pragma unroll
    for (int i = 0; i < 4; i++) {
        int idx = tid + i * 256;
        int r = idx >> 3, c = idx & 7;
        cp_async16(sb + r * 128 + ((c ^ (r & 7)) * 16),
                   qbh + (size_t)(w0 + r) * 64 + c * 8);
    }
    // Et tile (async): Et[d][i] = erh[d][w0+i], rows 256B swizzled
#pragma unroll
    for (int i = 0; i < 4; i++) {
        int idx = tid + i * 256;
        int d = idx >> 4, c16 = idx & 15;
        cp_async16(sb + 16384u + d * 256 + ((c16 >> 3) * 128) +
                   (((c16 & 7) ^ (d & 7)) * 16),
                   g_erh + d * 1024 + w0 + c16 * 8);
    }

    auto prefetch = [&](int ch, int stg) {
        const uint32_t kqb = sb + 32768u + stg * (uint32_t)ATTN_STAGE;
        const uint32_t vbb = kqb + 32768u;
        const __half* ksrc = kbh + (size_t)ch * 128 * 64;
        const __half* qsrc = qbh + (size_t)ch * 128 * 64;
#pragma unroll
        for (int i = 0; i < 8; i++) {
            int idx = tid + i * 256;
            int j = idx >> 4, c = idx & 15;
            const __half* src = ((c < 8) ? ksrc : qsrc) + j * 64 + (c & 7) * 8;
            cp_async16(kqb + j * 256 + ((c >> 3) * 128) +
                       (((c & 7) ^ (j & 7)) * 16), src);
        }
        const __half* vh = vhb + (size_t)ch * 128 * 64;
#pragma unroll
        for (int i = 0; i < 4; i++) {
            int idx = tid + i * 256;
            int u = idx >> 3, c = idx & 7;
            cp_async16(vbb + u * 128 + ((c ^ (u & 7)) * 16), vh + u * 64 + c * 8);
        }
    };
    prefetch(0, 0); CP_COMMIT();
    prefetch(1, 1); CP_COMMIT();

    float s[16][4];
    float o[2][8][4];
    float l[2][2] = {{0.f, 0.f}, {0.f, 0.f}};
#pragma unroll
    for (int mt = 0; mt < 2; mt++)
#pragma unroll
        for (int j = 0; j < 8; j++)
#pragma unroll
            for (int i = 0; i < 4; i++) o[mt][j][i] = 0.f;

    const int arow = (lane & 7) + ((lane >> 3) & 1) * 8;
    const int acs  = lane >> 4;
    const int brow = ((lane >> 4) << 3) + (lane & 7);
    const int bcs  = (lane >> 3) & 1;
    const int tm = lane >> 3, tr = lane & 7;
    const int i0 = warpM * 32;
    const int j0 = warpN * 64;

    for (int ch = 0; ch < 8; ch++) {
        if (ch == 7) { CP_WAIT(0); } else { CP_WAIT(1); }
        __syncthreads();
        if (ch + 2 < 8) { prefetch(ch + 2, (ch + 2) % 3); CP_COMMIT(); }

        const uint32_t kqb = sb + 32768u + (ch % 3) * (uint32_t)ATTN_STAGE;
        const uint32_t vhs = kqb + 32768u;

#pragma unroll
        for (int nt = 0; nt < 16; nt++)
#pragma unroll
            for (int i = 0; i < 4; i++) s[nt][i] = 0.f;

        // ---- S = [Qw|Et] @ [Ku|Qu]^T  (warp: rows i0..i0+32, cols j0..j0+64)
#pragma unroll
        for (int kb = 0; kb < 8; kb++) {
            uint32_t a[2][4];
#pragma unroll
            for (int mt = 0; mt < 2; mt++) {
                if (kb < 4) {
                    int row = i0 + mt * 16 + arow;
                    int chunk = kb * 2 + acs;
                    LDSM_X4(a[mt][0], a[mt][1], a[mt][2], a[mt][3],
                            sb + row * 128 + ((chunk ^ (row & 7)) * 16));
                } else {
                    int d = (kb - 4) * 16 + (tm >> 1) * 8 + tr;
                    int icol = i0 + mt * 16 + (tm & 1) * 8;
                    int c16 = icol >> 3;
                    LDSM_X4T(a[mt][0], a[mt][1], a[mt][2], a[mt][3],
                             sb + 16384 + d * 256 + ((c16 >> 3) * 128) +
                             (((c16 & 7) ^ (d & 7)) * 16));
                }
            }
#pragma unroll
            for (int np = 0; np < 4; np++) {
                uint32_t b0, b1, b2, b3;
                int j = j0 + np * 16 + brow;
                int chunk = kb * 2 + bcs;
                LDSM_X4(b0, b1, b2, b3,
                        kqb + j * 256 + ((chunk >> 3) * 128) +
                        (((chunk & 7) ^ (j & 7)) * 16));
#pragma unroll
                for (int mt = 0; mt < 2; mt++) {
                    mma_f16(s[mt * 8 + np * 2], a[mt], b0, b1);
                    mma_f16(s[mt * 8 + np * 2 + 1], a[mt], b2, b3);
                }
            }
        }

        // ---- exp2 + per-lane partial row sums (reduced once in epilogue)
#pragma unroll
        for (int mt = 0; mt < 2; mt++)
#pragma unroll
            for (int t = 0; t < 8; t++) {
                float* c = s[mt * 8 + t];
                c[0] = exp2f(c[0]); c[1] = exp2f(c[1]);
                c[2] = exp2f(c[2]); c[3] = exp2f(c[3]);
                l[mt][0] += c[0] + c[1];
                l[mt][1] += c[2] + c[3];
            }

        // ---- O += P @ V  (warp's u-range j0..j0+64, full d 0..63)
#pragma unroll
        for (int ku = 0; ku < 4; ku++) {
            uint32_t ah[2][4];
#pragma unroll
            for (int mt = 0; mt < 2; mt++) {
                float* p0 = s[mt * 8 + ku * 2];
                float* p1 = s[mt * 8 + ku * 2 + 1];
                ah[mt][0] = pkh(p0[0], p0[1]); ah[mt][1] = pkh(p0[2], p0[3]);
                ah[mt][2] = pkh(p1[0], p1[1]); ah[mt][3] = pkh(p1[2], p1[3]);
            }
            int u = j0 + ku * 16 + (tm & 1) * 8 + tr;
#pragma unroll
            for (int np = 0; np < 4; np++) {
                int d0 = np * 16 + (tm >> 1) * 8;
                int chunk = d0 >> 3;
                uint32_t off = u * 128 + ((chunk ^ (u & 7)) * 16);
                uint32_t v0, v1, v2, v3;
                LDSM_X4T(v0, v1, v2, v3, vhs + off);
#pragma unroll
                for (int mt = 0; mt < 2; mt++) {
                    mma_f16(o[mt][np * 2], ah[mt], v0, v1);
                    mma_f16(o[mt][np * 2 + 1], ah[mt], v2, v3);
                }
            }
        }
    }

    // ---- reduce l across the 4 column lanes of each row group
#pragma unroll
    for (int mt = 0; mt < 2; mt++)
#pragma unroll
        for (int r = 0; r < 2; r++) {
            l[mt][r] += __shfl_xor_sync(0xffffffffu, l[mt][r], 1);
            l[mt][r] += __shfl_xor_sync(0xffffffffu, l[mt][r], 2);
        }

    // ---- combine the two N-half partials via smem, then write out
    __syncthreads();                 // all stage/Qw/Et reads done
    float* smL = (float*)sm;                       // 128 floats (over Qw)
    float* smO = (float*)(sm + 32768);             // [128][stride 66] fp32
    const int g = lane >> 2, cp = (lane & 3) * 2;

    if (warpN == 1) {
#pragma unroll
        for (int mt = 0; mt < 2; mt++) {
            int r0 = i0 + mt * 16 + g;
#pragma unroll
            for (int j = 0; j < 8; j++) {
                int col = j * 8 + cp;
                *(float2*)&smO[r0 * 66 + col] =
                    make_float2(o[mt][j][0], o[mt][j][1]);
                *(float2*)&smO[(r0 + 8) * 66 + col] =
                    make_float2(o[mt][j][2], o[mt][j][3]);
            }
            if ((lane & 3) == 0) {
                smL[r0] = l[mt][0];
                smL[r0 + 8] = l[mt][1];
            }
        }
    }
    __syncthreads();
    if (warpN == 0) {
#pragma unroll
        for (int mt = 0; mt < 2; mt++) {
            int r0 = i0 + mt * 16 + g;
            float inv0 = 1.f / (l[mt][0] + smL[r0]);
            float inv1 = 1.f / (l[mt][1] + smL[r0 + 8]);
            const size_t base0 = ((size_t)b * W_ + (w0 + r0)) * C_ + h * 64;
            const size_t base1 = base0 + (size_t)8 * C_;
#pragma unroll
            for (int j = 0; j < 8; j++) {
                int col = j * 8 + cp;
                float2 p0 = *(float2*)&smO[r0 * 66 + col];
                float2 p1 = *(float2*)&smO[(r0 + 8) * 66 + col];
                *(uint32_t*)(g_avh + base0 + col) =
                    pkh((o[mt][j][0] + p0.x) * inv0, (o[mt][j][1] + p0.y) * inv0);
                *(uint32_t*)(g_avh + base1 + col) =
                    pkh((o[mt][j][2] + p1.x) * inv1, (o[mt][j][3] + p1.y) * inv1);
            }
        }
    }
}

// ---------------------------------------------------------------------------
extern "C" void kernel_launch(void* const* d_in, const int* in_sizes, int n_in,
                              void* d_out, int out_size) {
    const float* x  = (const float*)d_in[0];
    const float* Wq = (const float*)d_in[1];
    const float* bq = (const float*)d_in[2];
    const float* Wk = (const float*)d_in[3];
    const float* bk = (const float*)d_in[4];
    const float* Wv = (const float*)d_in[5];
    const float* bv = (const float*)d_in[6];
    const float* Wo = (const float*)d_in[7];
    const float* bo = (const float*)d_in[8];
    const float* er = (const float*)d_in[9];
    float* out = (float*)d_out;

    cudaFuncSetAttribute(gemm_f16a<0>, cudaFuncAttributeMaxDynamicSharedMemorySize, GEMM_SMEM);
    cudaFuncSetAttribute(gemm_f16a<1>, cudaFuncAttributeMaxDynamicSharedMemorySize, GEMM_SMEM);
    cudaFuncSetAttribute(attn_mma, cudaFuncAttributeMaxDynamicSharedMemorySize, ATTN_SMEM);

    cvt_all<<<8256, 256>>>(x, Wq, Wk, Wv, Wo, er);

    gemm_f16a<0><<<dim3(8, 32, 3), 256, GEMM_SMEM>>>(bq, bk, bv, nullptr);

    attn_mma<<<dim3(8, 64), 256, ATTN_SMEM>>>();

    gemm_f16a<1><<<dim3(8, 32), 256, GEMM_SMEM>>>(bo, nullptr, nullptr, out);
}